// round 17
// baseline (speedup 1.0000x reference)
#include <cuda_runtime.h>
#include <cuda_fp16.h>
#include <cstdint>

// ---------------- problem constants ----------------
constexpr int B    = 2048;
constexpr int S    = 24;
constexpr int T    = 25;
constexpr int H    = 256;
constexpr int E    = 300;
constexpr int VIN  = 300;
constexpr int VOUTD= 128;
constexpr int H3   = 3 * H;      // 768
constexpr int DH   = 2 * H;      // 512
constexpr int GHQ  = H3 + H;     // 1024 (gh | q)
constexpr int NBIG = VOUTD + GHQ;// 1152 fused decoder GEMM width

// ---------------- scratch (static device, no allocation) ----------------
__device__ float d_tabF [VIN * H3];
__device__ float d_tabB [VIN * H3];
__device__ float d_tabGi[VOUTD * H3];
__device__ float d_tabLg[VOUTD * VOUTD];
__device__ float d_h2   [2 * B * H];
__device__ float d_gh2  [2 * B * H3];
__device__ float d_encbse[B * S * DH];
__device__ __half d_encbse_h[B * S * DH];
__device__ float d_hcat [B * DH];
__device__ float d_hid  [B * H];
__device__ __half d_eproj_h[B * S * H];
__device__ float d_w    [B * DH];
__device__ float d_wlg  [B * VOUTD];         // weighted @ fcW[256:768]
__device__ float d_gi   [B * H3];
__device__ float d_ghq  [B * GHQ];           // [gh(768) | q(256)]
__device__ float d_WBIG [H * NBIG];          // [fcW(0:256) | dWhh | attn_Wh], tf32-rounded
// tf32-pre-rounded weight copies (mma B operands on the hot path)
__device__ float d_Whh2 [2 * H * H3];        // fwd | bwd
__device__ float d_Wgi  [DH * H3];           // dWih rows E..E+DH
__device__ float d_Wlg  [DH * VOUTD];        // fcW rows H..H+DH
__device__ float d_Wefc [DH * H];            // enc_fcW
__device__ float d_WaWe [DH * H];            // attn_We
__device__ float d_bBIG [NBIG];              // [fcb | dbhh | 0]

__device__ __forceinline__ float sigmoidf(float x) { return 1.f / (1.f + expf(-x)); }
__device__ __forceinline__ float tanh_fast(float x) {
    float y; asm("tanh.approx.f32 %0, %1;" : "=f"(y) : "f"(x)); return y;
}
__device__ __forceinline__ uint32_t f2tf(float x) {
    uint32_t u; asm("cvt.rna.tf32.f32 %0, %1;" : "=r"(u) : "f"(x)); return u;
}

// ---------------- TF32 tensor-core GEMM, 4-stage cp.async pipeline ----------------
struct GA {
    const float* A;     // M x K (lda=K)
    const float* W;     // K x N (ldb=ldw)
    const float* bias;  // N or null
    const float* gadd;  // gather-add table or null (row stride: N for act!=2, VOUTD for act==2)
    const int*   gidx;  // per-row index or null
    float*       C;     // output (act!=2: M x N; act==2: ghq region M x 1024)
    int M, N, K, ldw;
    int act;            // 0 none, 1 tanh, 2 fused-decoder epilogue, 3 half output to C2
    int cvtB;           // 1: apply cvt.rna.tf32 to B fragments (W not pre-rounded)
    const float* add0;  // act==2: per-row add for cols<128 (M x 128)
    void*        C2;    // act==2: logits out (float, M x 128); act==3: half out (M x N)
};

constexpr int STAGES = 4;
constexpr int GBM = 128, GBN = 64, GBK = 32;
constexpr int ASTR = GBK + 4;          // 36 words/row, 144 B (16B aligned)
constexpr int BSTR = GBN + 8;          // 72 words/row, 288 B (16B aligned)
constexpr int ASZ  = GBM * ASTR;       // floats per stage
constexpr int BSZ  = GBK * BSTR;
constexpr int GEMM_SMEM = STAGES * (ASZ + BSZ) * 4;   // 110592 B

__device__ __forceinline__ uint32_t smem_u32(const void* p) {
    return (uint32_t)__cvta_generic_to_shared(p);
}
__device__ __forceinline__ void cp16(uint32_t dst, const float* src, bool valid) {
    int b = valid ? 16 : 0;
    asm volatile("cp.async.ca.shared.global [%0], [%1], 16, %2;" :: "r"(dst), "l"(src), "r"(b));
}

__device__ __forceinline__ void mma8(float* c, const uint32_t* a, const uint32_t* b) {
    asm volatile(
        "mma.sync.aligned.m16n8k8.row.col.f32.tf32.tf32.f32 "
        "{%0,%1,%2,%3}, {%4,%5,%6,%7}, {%8,%9}, {%0,%1,%2,%3};"
        : "+f"(c[0]), "+f"(c[1]), "+f"(c[2]), "+f"(c[3])
        : "r"(a[0]), "r"(a[1]), "r"(a[2]), "r"(a[3]), "r"(b[0]), "r"(b[1]));
}

__device__ __forceinline__ void gemm_body(const GA g) {
    extern __shared__ float smf[];
    float* Asm = smf;                    // [STAGES][ASZ]
    float* Bsm = smf + STAGES * ASZ;     // [STAGES][BSZ]

    const int tid  = threadIdx.x;
    const int row0 = blockIdx.y * GBM;
    const int col0 = blockIdx.x * GBN;
    if (row0 >= g.M || col0 >= g.N) return;

    const int lane = tid & 31, warp = tid >> 5;
    const int wm = (warp >> 1) * 32;
    const int wn = (warp & 1) * 32;
    const int fr = lane >> 2;
    const int fc = lane & 3;

    const uint32_t aBase = smem_u32(Asm);
    const uint32_t bBase = smem_u32(Bsm);
    const int nk = (g.K + GBK - 1) / GBK;

    auto load = [&](int s, int kt) {
        const int k0 = kt * GBK;
        const uint32_t ab = aBase + (uint32_t)s * ASZ * 4;
        #pragma unroll
        for (int i = 0; i < 4; i++) {
            int idx = tid + i * 256;
            int rr = idx >> 3, cc = (idx & 7) * 4;
            int gr = row0 + rr, gc = k0 + cc;
            bool v = (gr < g.M) && (gc < g.K);      // K % 4 == 0 at all call sites
            const float* src = v ? &g.A[(size_t)gr * g.K + gc] : g.A;
            cp16(ab + (uint32_t)(rr * ASTR + cc) * 4, src, v);
        }
        const uint32_t bb = bBase + (uint32_t)s * BSZ * 4;
        #pragma unroll
        for (int i = 0; i < 2; i++) {
            int idx = tid + i * 256;
            int rr = idx >> 4, cc = (idx & 15) * 4;
            int gr = k0 + rr;
            bool v = (gr < g.K);                    // N % 64 == 0 at all call sites
            const float* src = v ? &g.W[(size_t)gr * g.ldw + col0 + cc] : g.W;
            cp16(bb + (uint32_t)(rr * BSTR + cc) * 4, src, v);
        }
    };

    float acc[2][4][4] = {};

    #pragma unroll
    for (int s = 0; s < STAGES - 1; s++) {
        if (s < nk) load(s, s);
        asm volatile("cp.async.commit_group;");
    }

    for (int kt = 0; kt < nk; kt++) {
        asm volatile("cp.async.wait_group %0;" :: "n"(STAGES - 2));
        __syncthreads();
        const int nx = kt + STAGES - 1;
        if (nx < nk) load(nx % STAGES, nx);
        asm volatile("cp.async.commit_group;");

        const float* A  = Asm + (kt % STAGES) * ASZ;
        const float* Bb = Bsm + (kt % STAGES) * BSZ;
        #pragma unroll
        for (int ks = 0; ks < 4; ks++) {
            const int k8 = ks * 8;
            uint32_t af[2][4], bf[4][2];
            #pragma unroll
            for (int i = 0; i < 2; i++) {
                const float* ap = &A[(wm + i * 16 + fr) * ASTR + k8 + fc];
                af[i][0] = f2tf(ap[0]);
                af[i][1] = f2tf(ap[8 * ASTR]);
                af[i][2] = f2tf(ap[4]);
                af[i][3] = f2tf(ap[8 * ASTR + 4]);
            }
            #pragma unroll
            for (int j = 0; j < 4; j++) {
                const float* bp = &Bb[(k8 + fc) * BSTR + wn + j * 8 + fr];
                if (g.cvtB) {
                    bf[j][0] = f2tf(bp[0]);
                    bf[j][1] = f2tf(bp[4 * BSTR]);
                } else {
                    bf[j][0] = __float_as_uint(bp[0]);
                    bf[j][1] = __float_as_uint(bp[4 * BSTR]);
                }
            }
            #pragma unroll
            for (int i = 0; i < 2; i++)
                #pragma unroll
                for (int j = 0; j < 4; j++)
                    mma8(acc[i][j], af[i], bf[j]);
        }
    }

    const bool isLogit = (g.act == 2) && (col0 < VOUTD);
    const int gstride = (g.act == 2) ? VOUTD : g.N;
    #pragma unroll
    for (int i = 0; i < 2; i++) {
        #pragma unroll
        for (int half = 0; half < 2; half++) {
            const int r = row0 + wm + i * 16 + fr + half * 8;
            if (r >= g.M) continue;
            const float* grow = nullptr;
            if (g.gidx && (g.act != 2 || isLogit))
                grow = &g.gadd[(size_t)g.gidx[r] * gstride];
            #pragma unroll
            for (int j = 0; j < 4; j++) {
                const int c = col0 + wn + j * 8 + fc * 2;
                float v0 = acc[i][j][half * 2 + 0];
                float v1 = acc[i][j][half * 2 + 1];
                if (g.bias) { v0 += g.bias[c]; v1 += g.bias[c + 1]; }
                if (g.act == 2) {
                    if (isLogit) {
                        v0 += grow[c] + g.add0[(size_t)r * VOUTD + c];
                        v1 += grow[c + 1] + g.add0[(size_t)r * VOUTD + c + 1];
                        *reinterpret_cast<float2*>(&((float*)g.C2)[(size_t)r * VOUTD + c]) = make_float2(v0, v1);
                    } else {
                        *reinterpret_cast<float2*>(&g.C[(size_t)r * GHQ + (c - VOUTD)]) = make_float2(v0, v1);
                    }
                } else if (g.act == 3) {
                    *reinterpret_cast<__half2*>(&((__half*)g.C2)[(size_t)r * g.N + c]) =
                        __floats2half2_rn(v0, v1);
                } else {
                    if (grow) { v0 += grow[c]; v1 += grow[c + 1]; }
                    if (g.act == 1) { v0 = tanhf(v0); v1 = tanhf(v1); }
                    *reinterpret_cast<float2*>(&g.C[(size_t)r * g.N + c]) = make_float2(v0, v1);
                }
            }
        }
    }
}

__global__ void __launch_bounds__(256) gemm1(GA g)         { gemm_body(g); }
__global__ void __launch_bounds__(256) gemm2(GA g0, GA g1) { gemm_body(blockIdx.z ? g1 : g0); }

// ---------------- small kernels ----------------
__global__ void zero_kernel(float* p, int n) {
    int i = blockIdx.x * blockDim.x + threadIdx.x;
    if (i < n) p[i] = 0.f;
}

__global__ void round_tf32(const float* __restrict__ in, float* __restrict__ out, int n) {
    int i = blockIdx.x * blockDim.x + threadIdx.x;
    if (i < n) out[i] = __uint_as_float(f2tf(in[i]));
}

__global__ void build_wbig(const float* __restrict__ fcW, const float* __restrict__ dWhh,
                           const float* __restrict__ aWh) {
    int i = blockIdx.x * blockDim.x + threadIdx.x;
    if (i >= H * NBIG) return;
    int r = i / NBIG, c = i - r * NBIG;
    float v;
    if (c < VOUTD)            v = fcW [r * VOUTD + c];
    else if (c < VOUTD + H3)  v = dWhh[r * H3 + (c - VOUTD)];
    else                      v = aWh [r * H + (c - VOUTD - H3)];
    d_WBIG[i] = __uint_as_float(f2tf(v));
}
__global__ void build_bbig(const float* __restrict__ fcb, const float* __restrict__ dbhh) {
    int i = blockIdx.x * blockDim.x + threadIdx.x;
    if (i >= NBIG) return;
    d_bBIG[i] = (i < VOUTD) ? fcb[i] : (i < VOUTD + H3 ? dbhh[i - VOUTD] : 0.f);
}

// encoder GRU gate, both directions; gi gathered from vocab table
__global__ void enc_gate_kernel(const int* __restrict__ src, int t) {
    int i = blockIdx.x * blockDim.x + threadIdx.x;
    if (i >= 2 * B * H) return;
    int dir = i / (B * H);
    int rem = i - dir * (B * H);
    int b = rem / H, j = rem - b * H;

    int srow = dir ? (S - 1 - t) : t;
    int tok  = src[srow * B + b];
    const float* gi = (dir ? d_tabB : d_tabF) + (size_t)tok * H3;
    const float* gh = d_gh2 + ((size_t)dir * B + b) * H3;

    float h  = d_h2[i];
    float r  = sigmoidf(gi[j]         + gh[j]);
    float z  = sigmoidf(gi[j + H]     + gh[j + H]);
    float n  = tanhf  (gi[j + 2 * H] + r * gh[j + 2 * H]);
    float hn = (1.f - z) * n + z * h;
    d_h2[i] = hn;
    size_t oidx = ((size_t)b * S + srow) * DH + dir * H + j;
    d_encbse[oidx]   = hn;
    d_encbse_h[oidx] = __float2half(hn);
}

__global__ void hcat_kernel() {
    int i = blockIdx.x * blockDim.x + threadIdx.x;
    if (i >= B * DH) return;
    int b = i / DH, j = i - b * DH;
    d_hcat[i] = d_h2[(j < H ? 0 : 1) * B * H + b * H + (j & (H - 1))];
}

// fused attention: energy(tanh.approx) + softmax + weighted sum, fp16 inputs.
__global__ void __launch_bounds__(256) attn_kernel(const float* __restrict__ ab,
                                                   const float* __restrict__ av) {
    const int b   = blockIdx.x;
    const int tid = threadIdx.x;
    __shared__ float qs[H], avs[H], sc[S], aw[S];

    qs[tid]  = d_ghq[(size_t)b * GHQ + H3 + tid] + ab[tid];
    avs[tid] = av[tid];
    __syncthreads();

    const int warp = tid >> 5, lane = tid & 31;
    const __half2* eph = reinterpret_cast<const __half2*>(d_eproj_h);
    for (int s = warp; s < S; s += 8) {
        const __half2* ep2 = eph + (size_t)(b * S + s) * (H / 2);
        float acc = 0.f;
        #pragma unroll
        for (int j = lane; j < H / 2; j += 32) {
            float2 f = __half22float2(ep2[j]);
            acc += tanh_fast(qs[2 * j]     + f.x) * avs[2 * j]
                 + tanh_fast(qs[2 * j + 1] + f.y) * avs[2 * j + 1];
        }
        #pragma unroll
        for (int o = 16; o; o >>= 1) acc += __shfl_down_sync(0xFFFFFFFFu, acc, o);
        if (lane == 0) sc[s] = acc;
    }
    __syncthreads();

    if (tid == 0) {
        float m = sc[0];
        #pragma unroll
        for (int s = 1; s < S; s++) m = fmaxf(m, sc[s]);
        float sum = 0.f;
        #pragma unroll
        for (int s = 0; s < S; s++) { float e = expf(sc[s] - m); aw[s] = e; sum += e; }
        float inv = 1.f / sum;
        #pragma unroll
        for (int s = 0; s < S; s++) aw[s] *= inv;
    }
    __syncthreads();

    const __half2* eb2 = reinterpret_cast<const __half2*>(d_encbse_h)
                       + (size_t)b * S * (DH / 2) + tid;
    float2 w = make_float2(0.f, 0.f);
    #pragma unroll
    for (int s = 0; s < S; s++) {
        float2 e = __half22float2(eb2[(size_t)s * (DH / 2)]);
        w.x += aw[s] * e.x;
        w.y += aw[s] * e.y;
    }
    *reinterpret_cast<float2*>(&d_w[(size_t)b * DH + 2 * tid]) = w;
}

__global__ void dec_gate_kernel() {
    int i = blockIdx.x * blockDim.x + threadIdx.x;
    if (i >= B * H) return;
    int b = i / H, j = i - b * H;
    const float* gi = d_gi  + (size_t)b * H3;
    const float* gh = d_ghq + (size_t)b * GHQ;
    float h  = d_hid[i];
    float r  = sigmoidf(gi[j]         + gh[j]);
    float z  = sigmoidf(gi[j + H]     + gh[j + H]);
    float n  = tanhf  (gi[j + 2 * H] + r * gh[j + 2 * H]);
    d_hid[i] = (1.f - z) * n + z * h;
}

// ---------------- host ----------------
static float* sym_addr(const void* symbol) {
    void* p = nullptr;
    cudaGetSymbolAddress(&p, symbol);
    return (float*)p;
}
static inline int cdiv(int a, int b) { return (a + b - 1) / b; }

static GA mk(const float* A, const float* W, const float* bias, const float* gadd,
             const int* gidx, float* C, int M, int N, int K, int ldw, int act, int cvtB,
             const float* add0 = nullptr, void* C2 = nullptr) {
    GA g; g.A = A; g.W = W; g.bias = bias; g.gadd = gadd; g.gidx = gidx;
    g.C = C; g.M = M; g.N = N; g.K = K; g.ldw = ldw; g.act = act; g.cvtB = cvtB;
    g.add0 = add0; g.C2 = C2; return g;
}

static void launch1(const GA& g) {
    dim3 gr(cdiv(g.N, GBN), cdiv(g.M, GBM));
    gemm1<<<gr, 256, GEMM_SMEM>>>(g);
}
static void launch2(const GA& g0, const GA& g1) {
    dim3 gr(max(cdiv(g0.N, GBN), cdiv(g1.N, GBN)),
            max(cdiv(g0.M, GBM), cdiv(g1.M, GBM)), 2);
    gemm2<<<gr, 256, GEMM_SMEM>>>(g0, g1);
}

extern "C" void kernel_launch(void* const* d_in, const int* in_sizes, int n_in,
                              void* d_out, int out_size) {
    const int*   src    = (const int*)  d_in[0];
    const int*   trg    = (const int*)  d_in[1];
    const float* eemb   = (const float*)d_in[2];
    const float* Wih_f  = (const float*)d_in[3];
    const float* Whh_f  = (const float*)d_in[4];
    const float* bih_f  = (const float*)d_in[5];
    const float* bhh_f  = (const float*)d_in[6];
    const float* Wih_b  = (const float*)d_in[7];
    const float* Whh_b  = (const float*)d_in[8];
    const float* bih_b  = (const float*)d_in[9];
    const float* bhh_b  = (const float*)d_in[10];
    const float* efcW   = (const float*)d_in[11];
    const float* efcb   = (const float*)d_in[12];
    const float* aWh    = (const float*)d_in[13];
    const float* aWe    = (const float*)d_in[14];
    const float* ab     = (const float*)d_in[15];
    const float* av     = (const float*)d_in[16];
    const float* demb   = (const float*)d_in[17];
    const float* dWih   = (const float*)d_in[18];
    const float* dWhh   = (const float*)d_in[19];
    const float* dbih   = (const float*)d_in[20];
    const float* dbhh   = (const float*)d_in[21];
    const float* fcW    = (const float*)d_in[22];
    const float* fcb    = (const float*)d_in[23];
    float* out = (float*)d_out;

    cudaFuncSetAttribute(gemm1, cudaFuncAttributeMaxDynamicSharedMemorySize, GEMM_SMEM);
    cudaFuncSetAttribute(gemm2, cudaFuncAttributeMaxDynamicSharedMemorySize, GEMM_SMEM);

    float* ptabF   = sym_addr(d_tabF);
    float* ptabB   = sym_addr(d_tabB);
    float* ptabGi  = sym_addr(d_tabGi);
    float* ptabLg  = sym_addr(d_tabLg);
    float* ph2     = sym_addr(d_h2);
    float* pgh2    = sym_addr(d_gh2);
    float* pencbse = sym_addr(d_encbse);
    float* phcat   = sym_addr(d_hcat);
    float* phid    = sym_addr(d_hid);
    void*  peprojh = (void*)sym_addr(d_eproj_h);
    float* pw      = sym_addr(d_w);
    float* pwlg    = sym_addr(d_wlg);
    float* pgi     = sym_addr(d_gi);
    float* pghq    = sym_addr(d_ghq);
    float* pWBIG   = sym_addr(d_WBIG);
    float* pbBIG   = sym_addr(d_bBIG);
    float* pWhh2   = sym_addr(d_Whh2);
    float* pWgi    = sym_addr(d_Wgi);
    float* pWlg    = sym_addr(d_Wlg);
    float* pWefc   = sym_addr(d_Wefc);
    float* pWaWe   = sym_addr(d_WaWe);

    // init
    zero_kernel<<<cdiv(2 * B * H, 256), 256>>>(ph2, 2 * B * H);
    zero_kernel<<<cdiv(B * VOUTD, 256), 256>>>(out, B * VOUTD);

    // tf32 pre-rounded weight copies (hot-path mma B operands)
    round_tf32<<<cdiv(H * H3, 256), 256>>>(Whh_f, pWhh2, H * H3);
    round_tf32<<<cdiv(H * H3, 256), 256>>>(Whh_b, pWhh2 + H * H3, H * H3);
    round_tf32<<<cdiv(DH * H3, 256), 256>>>(dWih + (size_t)E * H3, pWgi, DH * H3);
    round_tf32<<<cdiv(DH * VOUTD, 256), 256>>>(fcW + (size_t)H * VOUTD, pWlg, DH * VOUTD);
    round_tf32<<<cdiv(DH * H, 256), 256>>>(efcW, pWefc, DH * H);
    round_tf32<<<cdiv(DH * H, 256), 256>>>(aWe, pWaWe, DH * H);
    build_wbig<<<cdiv(H * NBIG, 256), 256>>>(fcW, dWhh, aWh);
    build_bbig<<<cdiv(NBIG, 256), 256>>>(fcb, dbhh);

    // vocab tables (preamble-only: cvtB=1 against original weights)
    launch2(mk(eemb, Wih_f, bih_f, nullptr, nullptr, ptabF, VIN, H3, E, H3, 0, 1),
            mk(eemb, Wih_b, bih_b, nullptr, nullptr, ptabB, VIN, H3, E, H3, 0, 1));
    launch2(mk(demb, dWih, nullptr, nullptr, nullptr, ptabGi, VOUTD, H3, E, H3, 0, 1),
            mk(demb, fcW + (size_t)(H + DH) * VOUTD, nullptr, nullptr, nullptr,
               ptabLg, VOUTD, VOUTD, E, VOUTD, 0, 1));

    // encoder recurrent scan (fwd + bwd fused)
    for (int t = 0; t < S; t++) {
        launch2(mk(ph2,         pWhh2,          bhh_f, nullptr, nullptr, pgh2,          B, H3, H, H3, 0, 0),
                mk(ph2 + B * H, pWhh2 + H * H3, bhh_b, nullptr, nullptr, pgh2 + B * H3, B, H3, H, H3, 0, 0));
        enc_gate_kernel<<<cdiv(2 * B * H, 256), 256>>>(src, t);
    }

    // decoder initial hidden + enc_proj (half output) + first ghq
    hcat_kernel<<<cdiv(B * DH, 256), 256>>>();
    launch1(mk(phcat, pWefc, efcb, nullptr, nullptr, phid, B, H, DH, H, 1, 0));
    launch1(mk(pencbse, pWaWe, nullptr, nullptr, nullptr, nullptr, B * S, H, DH, H, 3, 0,
               nullptr, peprojh));
    launch1(mk(phid, pWBIG + VOUTD, pbBIG + VOUTD, nullptr, nullptr, pghq, B, GHQ, H, NBIG, 0, 0));

    // decoder scan
    for (int t = 0; t < T - 1; t++) {
        attn_kernel<<<B, 256>>>(ab, av);
        // gi = weighted @ dWih[E:] + bih + tabGi[trg_t] ; wlg = weighted @ fcW[256:768]
        launch2(mk(pw, pWgi, dbih, ptabGi, trg + t * B, pgi, B, H3, DH, H3, 0, 0),
                mk(pw, pWlg, nullptr, nullptr, nullptr, pwlg, B, VOUTD, DH, VOUTD, 0, 0));
        dec_gate_kernel<<<cdiv(B * H, 256), 256>>>();
        // fused: [logits | gh | q] = hn @ WBIG ; logits += wlg + fcb + tabLg[trg_t]
        launch1(mk(phid, pWBIG, pbBIG, ptabLg, trg + t * B, pghq, B, NBIG, H, NBIG, 2, 0,
                   pwlg, (void*)(out + (size_t)(t + 1) * B * VOUTD)));
    }
}